// round 4
// baseline (speedup 1.0000x reference)
#include <cuda_runtime.h>
#include <cuda_bf16.h>
#include <math.h>
#include <stdint.h>

// Problem constants (fixed by the dataset)
#define BATCH 8
#define NPTS  2048
#define DIM   512
#define KN    3
#define NROWS (BATCH * NPTS)   // 16384
#define FCK   1536             // split-precision fc: 3 * DIM

// ---------------- scratch (static device memory; no allocs allowed) ----------
__device__ float         g_xn [(size_t)NROWS * DIM];            // 32 MB fp32 normalized
__device__ __nv_bfloat16 g_xnb[(size_t)NROWS * DIM];            // 16 MB bf16 normalized
__device__ float         g_dis[(size_t)BATCH * NPTS * NPTS];    // 134 MB scores
__device__ int           g_idx8[(size_t)NROWS * 8];
__device__ int           g_idx [(size_t)NROWS * KN];
__device__ float         g_pooled[(size_t)NROWS * DIM];         // 32 MB
__device__ __nv_bfloat16 g_fcA[(size_t)NROWS * FCK];            // 48 MB  [hi, hi, lo]
__device__ __nv_bfloat16 g_fcB[(size_t)DIM * FCK];              // 1.5 MB [hi, lo, hi]

// ============================ PTX helpers ======================================
__device__ __forceinline__ uint32_t smem_u32(const void* p) {
    uint32_t a;
    asm("{ .reg .u64 t; cvta.to.shared.u64 t, %1; cvt.u32.u64 %0, t; }"
        : "=r"(a) : "l"(p));
    return a;
}

#define CP_ASYNC16(saddr, gptr) \
    asm volatile("cp.async.cg.shared.global [%0], [%1], 16;" \
                 :: "r"(saddr), "l"(gptr) : "memory")
#define CP_COMMIT()  asm volatile("cp.async.commit_group;" ::: "memory")
#define CP_WAIT1()   asm volatile("cp.async.wait_group 1;" ::: "memory")
#define CP_WAIT0()   asm volatile("cp.async.wait_group 0;" ::: "memory")

#define LDMATRIX_X4(r, addr) \
    asm volatile("ldmatrix.sync.aligned.m8n8.x4.shared.b16 {%0,%1,%2,%3}, [%4];" \
        : "=r"((r)[0]), "=r"((r)[1]), "=r"((r)[2]), "=r"((r)[3]) : "r"(addr))

#define MMA_BF16(c, a, b0, b1) \
    asm volatile("mma.sync.aligned.m16n8k16.row.col.f32.bf16.bf16.f32 " \
        "{%0,%1,%2,%3}, {%4,%5,%6,%7}, {%8,%9}, {%0,%1,%2,%3};" \
        : "+f"((c)[0]), "+f"((c)[1]), "+f"((c)[2]), "+f"((c)[3]) \
        : "r"((a)[0]), "r"((a)[1]), "r"((a)[2]), "r"((a)[3]), "r"(b0), "r"(b1))

// ---------------- 1. row L2-normalize + bf16 copy -----------------------------
__global__ void __launch_bounds__(128) normalize_k(const float* __restrict__ feats)
{
    const size_t row = blockIdx.x;
    const float4 v = ((const float4*)(feats + row * DIM))[threadIdx.x];
    float ss = v.x * v.x + v.y * v.y + v.z * v.z + v.w * v.w;
    #pragma unroll
    for (int o = 16; o; o >>= 1) ss += __shfl_xor_sync(0xffffffffu, ss, o);
    __shared__ float s[4];
    if ((threadIdx.x & 31) == 0) s[threadIdx.x >> 5] = ss;
    __syncthreads();
    const float tot = s[0] + s[1] + s[2] + s[3];
    const float inv = 1.0f / fmaxf(sqrtf(tot), 1e-12f);
    float4 o4;
    o4.x = v.x * inv; o4.y = v.y * inv; o4.z = v.z * inv; o4.w = v.w * inv;
    ((float4*)(g_xn + row * DIM))[threadIdx.x] = o4;
    __nv_bfloat162 b0, b1;
    b0.x = __float2bfloat16(o4.x); b0.y = __float2bfloat16(o4.y);
    b1.x = __float2bfloat16(o4.z); b1.y = __float2bfloat16(o4.w);
    ((__nv_bfloat162*)(g_xnb + row * DIM))[threadIdx.x * 2]     = b0;
    ((__nv_bfloat162*)(g_xnb + row * DIM))[threadIdx.x * 2 + 1] = b1;
}

// ---------------- bf16 tensor-core GEMM: C = A * B^T (both K-major) -----------
template <int RELU>
__global__ void __launch_bounds__(256, 2) gemm_bf16_nt(
    const __nv_bfloat16* __restrict__ A, const __nv_bfloat16* __restrict__ B,
    float* __restrict__ C, int N, int K,
    long long strideA, long long strideB, long long strideC)
{
    extern __shared__ char smem_raw[];
    char* tiles = (char*)(((uintptr_t)smem_raw + 1023) & ~(uintptr_t)1023);
    const uint32_t sbase = smem_u32(tiles);

    A += (long long)blockIdx.z * strideA;
    B += (long long)blockIdx.z * strideB;
    C += (long long)blockIdx.z * strideC;

    const int tid  = threadIdx.x;
    const int lane = tid & 31, wid = tid >> 5;
    const int wr = wid >> 2, wc = wid & 3;     // 2 x 4 warp grid
    const int brow = blockIdx.y * 128, bcol = blockIdx.x * 128;

    const int seg = tid & 7;       // 16B segment within 128B row
    const int r0  = tid >> 3;      // 0..31

    const __nv_bfloat16* Ar = A + (size_t)brow * K;
    const __nv_bfloat16* Br = B + (size_t)bcol * K;

    auto load_chunk = [&](int c, int stage) {
        const uint32_t dA = sbase + stage * 32768;
        const uint32_t dB = dA + 16384;
        const size_t koff = (size_t)c * 64 + seg * 8;
        #pragma unroll
        for (int it = 0; it < 4; ++it) {
            const int r = r0 + it * 32;
            uint32_t off = r * 128 + seg * 16;
            off ^= (off >> 3) & 0x70;
            CP_ASYNC16(dA + off, Ar + (size_t)r * K + koff);
            CP_ASYNC16(dB + off, Br + (size_t)r * K + koff);
        }
    };

    float acc[4][4][4];
    #pragma unroll
    for (int mt = 0; mt < 4; ++mt)
        #pragma unroll
        for (int nt = 0; nt < 4; ++nt)
            #pragma unroll
            for (int q = 0; q < 4; ++q) acc[mt][nt][q] = 0.0f;

    const int nk = K >> 6;
    load_chunk(0, 0);
    CP_COMMIT();

    const int mi  = lane >> 3;
    const int l7  = lane & 7;

    #pragma unroll 1
    for (int c = 0; c < nk; ++c) {
        const int st = c & 1;
        if (c + 1 < nk) {
            load_chunk(c + 1, st ^ 1);
            CP_COMMIT();
            CP_WAIT1();
        } else {
            CP_WAIT0();
        }
        __syncthreads();

        const uint32_t tA = sbase + st * 32768;
        const uint32_t tB = tA + 16384;

        #pragma unroll
        for (int ks = 0; ks < 4; ++ks) {
            uint32_t a[4][4], b[2][4];
            #pragma unroll
            for (int mt = 0; mt < 4; ++mt) {
                const int row = wr * 64 + mt * 16 + l7 + ((mi & 1) << 3);
                const int sg  = ks * 2 + (mi >> 1);
                uint32_t off = row * 128 + sg * 16;
                off ^= (off >> 3) & 0x70;
                LDMATRIX_X4(a[mt], tA + off);
            }
            #pragma unroll
            for (int np = 0; np < 2; ++np) {
                const int n  = wc * 32 + np * 16 + l7 + ((mi >> 1) << 3);
                const int sg = ks * 2 + (mi & 1);
                uint32_t off = n * 128 + sg * 16;
                off ^= (off >> 3) & 0x70;
                LDMATRIX_X4(b[np], tB + off);
            }
            #pragma unroll
            for (int mt = 0; mt < 4; ++mt)
                #pragma unroll
                for (int nt = 0; nt < 4; ++nt)
                    MMA_BF16(acc[mt][nt], a[mt],
                             b[nt >> 1][(nt & 1) * 2], b[nt >> 1][(nt & 1) * 2 + 1]);
        }
        __syncthreads();
    }

    // epilogue
    const int rbase = brow + wr * 64 + (lane >> 2);
    const int cbase = bcol + wc * 32 + (lane & 3) * 2;
    #pragma unroll
    for (int mt = 0; mt < 4; ++mt) {
        #pragma unroll
        for (int nt = 0; nt < 4; ++nt) {
            float2 v0, v1;
            v0.x = acc[mt][nt][0]; v0.y = acc[mt][nt][1];
            v1.x = acc[mt][nt][2]; v1.y = acc[mt][nt][3];
            if (RELU) {
                v0.x = fmaxf(v0.x, 0.f); v0.y = fmaxf(v0.y, 0.f);
                v1.x = fmaxf(v1.x, 0.f); v1.y = fmaxf(v1.y, 0.f);
            }
            const int row = rbase + mt * 16;
            const int col = cbase + nt * 8;
            *(float2*)(C + (size_t)row * N + col)       = v0;
            *(float2*)(C + (size_t)(row + 8) * N + col) = v1;
        }
    }
}

// ---------------- ordering helpers (jax.lax.top_k: desc value, tie -> low idx) -
__device__ __forceinline__ bool pref(float v, int i, float v2, int i2)
{
    return (v > v2) || (v == v2 && i < i2);
}

__device__ __forceinline__ void ins3(float v, int i, float tv[3], int ti[3])
{
    if (!pref(v, i, tv[2], ti[2])) return;
    tv[2] = v; ti[2] = i;
    if (pref(tv[2], ti[2], tv[1], ti[1])) {
        float fv = tv[1]; int fi = ti[1];
        tv[1] = tv[2]; ti[1] = ti[2]; tv[2] = fv; ti[2] = fi;
    }
    if (pref(tv[1], ti[1], tv[0], ti[0])) {
        float fv = tv[0]; int fi = ti[0];
        tv[0] = tv[1]; ti[0] = ti[1]; tv[1] = fv; ti[1] = fi;
    }
}

// ---------------- 3a. top-8 candidates per row, warp-per-row, packed u64 ------
// key = (monotone(valbits) << 32) | ~idx  -> single u64 compare implements
// (desc value, tie -> lower index). Exactly the top-8 of the stored scores.
__device__ __forceinline__ unsigned long long pack_key(float v, int idx)
{
    uint32_t u = __float_as_uint(v);
    u = (u & 0x80000000u) ? ~u : (u | 0x80000000u);
    return ((unsigned long long)u << 32) | (uint32_t)(~idx);
}

__global__ void __launch_bounds__(256) top8_k(void)
{
    const int row  = blockIdx.x * 8 + (threadIdx.x >> 5);
    const int lane = threadIdx.x & 31;
    const float4* d = (const float4*)(g_dis + (size_t)row * NPTS);

    unsigned long long t[8];
    #pragma unroll
    for (int e = 0; e < 8; ++e) t[e] = 0ull;

    #pragma unroll 4
    for (int it = 0; it < 16; ++it) {
        const int f4 = it * 32 + lane;
        const float4 v = d[f4];
        const int base = f4 * 4;
        unsigned long long k;
        #pragma unroll
        for (int q = 0; q < 4; ++q) {
            const float val = (q == 0) ? v.x : (q == 1) ? v.y : (q == 2) ? v.z : v.w;
            k = pack_key(val, base + q);
            if (k > t[7]) {
                t[7] = k;
                #pragma unroll
                for (int e = 7; e > 0; --e) {
                    if (t[e] > t[e - 1]) {
                        unsigned long long tmp = t[e - 1];
                        t[e - 1] = t[e]; t[e] = tmp;
                    }
                }
            }
        }
    }

    // merge 32 sorted lists: 8 rounds of warp-wide max + pop
    int h = 0;
    int out[8];
    #pragma unroll
    for (int r = 0; r < 8; ++r) {
        unsigned long long cand = (h < 8) ? t[h] : 0ull;
        unsigned long long m = cand;
        #pragma unroll
        for (int o = 16; o; o >>= 1) {
            unsigned long long other = __shfl_xor_sync(0xffffffffu, m, o);
            if (other > m) m = other;
        }
        if (cand == m && h < 8) ++h;       // unique keys: exactly one lane pops
        out[r] = ~(uint32_t)m;
    }
    if (lane == 0) {
        #pragma unroll
        for (int e = 0; e < 8; ++e) g_idx8[(size_t)row * 8 + e] = out[e];
    }
}

// ---------------- 3b. exact fp32 rescore of the 8 candidates, pick top-3 ------
__global__ void __launch_bounds__(256) rescore_k(void)
{
    const int gw   = blockIdx.x * 8 + (threadIdx.x >> 5);   // row, 1 warp/row
    const int lane = threadIdx.x & 31;
    const int b    = gw >> 11;

    const float4* xrow = (const float4*)(g_xn + (size_t)gw * DIM);
    float4 x[4];
    #pragma unroll
    for (int q = 0; q < 4; ++q) x[q] = xrow[q * 32 + lane];

    float bv[3] = { -1e30f, -1e30f, -1e30f };
    int   bi[3] = { 0x7fffffff, 0x7fffffff, 0x7fffffff };

    #pragma unroll
    for (int c = 0; c < 8; ++c) {
        const int cand = g_idx8[(size_t)gw * 8 + c];
        const float4* yr = (const float4*)(g_xn + ((size_t)(b << 11) + cand) * DIM);
        float s = 0.0f;
        #pragma unroll
        for (int q = 0; q < 4; ++q) {
            const float4 y = yr[q * 32 + lane];
            s += x[q].x * y.x + x[q].y * y.y + x[q].z * y.z + x[q].w * y.w;
        }
        #pragma unroll
        for (int o = 16; o; o >>= 1) s += __shfl_xor_sync(0xffffffffu, s, o);
        ins3(s, cand, bv, bi);
    }
    if (lane == 0) {
        g_idx[gw * 3 + 0] = bi[0];
        g_idx[gw * 3 + 1] = bi[1];
        g_idx[gw * 3 + 2] = bi[2];
    }
}

// ---------------- 4. gather + conv-mapping + softmax + mean-pool --------------
__global__ void __launch_bounds__(256) conv_pool2_k(
    const float* __restrict__ feats,
    const float* __restrict__ convw,   // (3,3,512)
    const float* __restrict__ convb)   // (3,3)
{
    __shared__ float wsm[9 * DIM];      // 18 KB
    const int tid = threadIdx.x, lane = tid & 31, wid = tid >> 5;

    for (int i = tid; i < 9 * DIM / 4; i += 256)
        ((float4*)wsm)[i] = ((const float4*)convw)[i];
    __syncthreads();

    const int node = blockIdx.x * 8 + wid;
    const int b = node >> 11;
    const float* fb = feats + (size_t)b * NPTS * DIM;

    float4 kr[3][4];
    #pragma unroll
    for (int g = 0; g < 3; ++g) {
        const int id = g_idx[(size_t)node * 3 + g];
        const float4* yp = (const float4*)(fb + (size_t)id * DIM);
        #pragma unroll
        for (int q = 0; q < 4; ++q) kr[g][q] = yp[q * 32 + lane];
    }

    float p[9];
    #pragma unroll
    for (int q9 = 0; q9 < 9; ++q9) p[q9] = 0.0f;
    #pragma unroll
    for (int q = 0; q < 4; ++q) {
        const int col4 = q * 32 + lane;
        #pragma unroll
        for (int g = 0; g < 3; ++g) {
            const float4 kv = kr[g][q];
            #pragma unroll
            for (int j = 0; j < 3; ++j) {
                const float4 wv = ((const float4*)wsm)[(g * 3 + j) * 128 + col4];
                p[g * 3 + j] += kv.x * wv.x + kv.y * wv.y + kv.z * wv.z + kv.w * wv.w;
            }
        }
    }
    #pragma unroll
    for (int q9 = 0; q9 < 9; ++q9)
        #pragma unroll
        for (int o = 16; o; o >>= 1) p[q9] += __shfl_xor_sync(0xffffffffu, p[q9], o);

    float w0 = 0.f, w1 = 0.f, w2 = 0.f;
    #pragma unroll
    for (int g = 0; g < 3; ++g) {
        const float m0 = p[g * 3 + 0] + __ldg(convb + g * 3 + 0);
        const float m1 = p[g * 3 + 1] + __ldg(convb + g * 3 + 1);
        const float m2 = p[g * 3 + 2] + __ldg(convb + g * 3 + 2);
        const float mx = fmaxf(m0, fmaxf(m1, m2));
        const float e0 = expf(m0 - mx), e1 = expf(m1 - mx), e2 = expf(m2 - mx);
        const float inv = 1.0f / (e0 + e1 + e2);
        w0 += e0 * inv; w1 += e1 * inv; w2 += e2 * inv;
    }
    const float third = 1.0f / 3.0f;
    const float c0 = w0 * third, c1 = w1 * third, c2 = w2 * third;

    float* op = g_pooled + (size_t)node * DIM;
    #pragma unroll
    for (int q = 0; q < 4; ++q) {
        float4 o;
        o.x = c0 * kr[0][q].x + c1 * kr[1][q].x + c2 * kr[2][q].x;
        o.y = c0 * kr[0][q].y + c1 * kr[1][q].y + c2 * kr[2][q].y;
        o.z = c0 * kr[0][q].z + c1 * kr[1][q].z + c2 * kr[2][q].z;
        o.w = c0 * kr[0][q].w + c1 * kr[1][q].w + c2 * kr[2][q].w;
        ((float4*)op)[q * 32 + lane] = o;
    }
}

// ---------------- split fp32 -> [hi, hi, lo] / [hi, lo, hi] bf16 ---------------
__device__ __forceinline__ void split4(const float4 v,
                                       __nv_bfloat162& h01, __nv_bfloat162& h23,
                                       __nv_bfloat162& l01, __nv_bfloat162& l23)
{
    const __nv_bfloat16 h0 = __float2bfloat16(v.x);
    const __nv_bfloat16 h1 = __float2bfloat16(v.y);
    const __nv_bfloat16 h2 = __float2bfloat16(v.z);
    const __nv_bfloat16 h3 = __float2bfloat16(v.w);
    h01.x = h0; h01.y = h1; h23.x = h2; h23.y = h3;
    l01.x = __float2bfloat16(v.x - __bfloat162float(h0));
    l01.y = __float2bfloat16(v.y - __bfloat162float(h1));
    l23.x = __float2bfloat16(v.z - __bfloat162float(h2));
    l23.y = __float2bfloat16(v.w - __bfloat162float(h3));
}

__global__ void __launch_bounds__(128) splitA_k(void)
{
    const size_t row = blockIdx.x;
    const int c = threadIdx.x * 4;
    const float4 v = ((const float4*)(g_pooled + row * DIM))[threadIdx.x];
    __nv_bfloat162 h01, h23, l01, l23;
    split4(v, h01, h23, l01, l23);
    __nv_bfloat162* dst = (__nv_bfloat162*)(g_fcA + row * FCK);
    dst[(c) / 2]          = h01; dst[(c) / 2 + 1]          = h23;  // [0,512): hi
    dst[(c + 512) / 2]    = h01; dst[(c + 512) / 2 + 1]    = h23;  // [512,1024): hi
    dst[(c + 1024) / 2]   = l01; dst[(c + 1024) / 2 + 1]   = l23;  // [1024,1536): lo
}

__global__ void __launch_bounds__(128) splitB_k(const float* __restrict__ fcw)
{
    const size_t row = blockIdx.x;
    const int c = threadIdx.x * 4;
    const float4 v = ((const float4*)(fcw + row * DIM))[threadIdx.x];
    __nv_bfloat162 h01, h23, l01, l23;
    split4(v, h01, h23, l01, l23);
    __nv_bfloat162* dst = (__nv_bfloat162*)(g_fcB + row * FCK);
    dst[(c) / 2]          = h01; dst[(c) / 2 + 1]          = h23;  // [0,512): hi
    dst[(c + 512) / 2]    = l01; dst[(c + 512) / 2 + 1]    = l23;  // [512,1024): lo
    dst[(c + 1024) / 2]   = h01; dst[(c + 1024) / 2 + 1]   = h23;  // [1024,1536): hi
}

// ---------------- launch -------------------------------------------------------
extern "C" void kernel_launch(void* const* d_in, const int* in_sizes, int n_in,
                              void* d_out, int out_size)
{
    const float* feats = (const float*)d_in[0];
    const float* convw = (const float*)d_in[1];
    const float* convb = (const float*)d_in[2];
    const float* fcw   = (const float*)d_in[3];
    float* out = (float*)d_out;

    void *xnb_p, *dis_p, *fcA_p, *fcB_p;
    cudaGetSymbolAddress(&xnb_p, g_xnb);
    cudaGetSymbolAddress(&dis_p, g_dis);
    cudaGetSymbolAddress(&fcA_p, g_fcA);
    cudaGetSymbolAddress(&fcB_p, g_fcB);

    const int smem_bytes = 66 * 1024;
    cudaFuncSetAttribute(gemm_bf16_nt<0>,
                         cudaFuncAttributeMaxDynamicSharedMemorySize, smem_bytes);
    cudaFuncSetAttribute(gemm_bf16_nt<1>,
                         cudaFuncAttributeMaxDynamicSharedMemorySize, smem_bytes);

    // 1. normalize rows (fp32 + bf16 copies)
    normalize_k<<<NROWS, 128>>>(feats);

    // split fc weights early (independent)
    splitB_k<<<DIM, 128>>>(fcw);

    // 2. cosine similarity: bf16 mma.sync, fp32 accumulate
    {
        dim3 grid(NPTS / 128, NPTS / 128, BATCH);
        gemm_bf16_nt<0><<<grid, 256, smem_bytes>>>(
            (const __nv_bfloat16*)xnb_p, (const __nv_bfloat16*)xnb_p, (float*)dis_p,
            NPTS, DIM,
            (long long)NPTS * DIM, (long long)NPTS * DIM, (long long)NPTS * NPTS);
    }

    // 3. top-8 candidates (warp per row), then exact fp32 rescore -> top-3
    top8_k<<<NROWS / 8, 256>>>();
    rescore_k<<<NROWS / 8, 256>>>();

    // 4. gather + conv mapping + softmax + pool (warp per node)
    conv_pool2_k<<<NROWS / 8, 256>>>(feats, convw, convb);

    // 5. fc + relu: split-precision bf16 GEMM, K=1536
    splitA_k<<<NROWS, 128>>>();
    {
        dim3 grid(DIM / 128, NROWS / 128, 1);
        gemm_bf16_nt<1><<<grid, 256, smem_bytes>>>(
            (const __nv_bfloat16*)fcA_p, (const __nv_bfloat16*)fcB_p, out,
            DIM, FCK, 0, 0, 0);
    }
}

// round 5
// speedup vs baseline: 2.5409x; 2.5409x over previous
#include <cuda_runtime.h>
#include <cuda_bf16.h>
#include <math.h>
#include <stdint.h>

// Problem constants (fixed by the dataset)
#define BATCH 8
#define NPTS  2048
#define DIM   512
#define KN    3
#define NROWS (BATCH * NPTS)   // 16384
#define FCK   1536             // split-precision fc: 3 * DIM

// ---------------- scratch (static device memory; no allocs allowed) ----------
__device__ float         g_xn [(size_t)NROWS * DIM];            // 32 MB fp32 normalized
__device__ __nv_bfloat16 g_xnb[(size_t)NROWS * DIM];            // 16 MB bf16 normalized
__device__ float         g_dis[(size_t)BATCH * NPTS * NPTS];    // 134 MB scores
__device__ int           g_idx8[(size_t)NROWS * 8];
__device__ int           g_idx [(size_t)NROWS * KN];
__device__ float         g_pooled[(size_t)NROWS * DIM];         // 32 MB
__device__ __nv_bfloat16 g_fcA[(size_t)NROWS * FCK];            // 48 MB  [hi, hi, lo]
__device__ __nv_bfloat16 g_fcB[(size_t)DIM * FCK];              // 1.5 MB [hi, lo, hi]

// ============================ PTX helpers ======================================
__device__ __forceinline__ uint32_t smem_u32(const void* p) {
    uint32_t a;
    asm("{ .reg .u64 t; cvta.to.shared.u64 t, %1; cvt.u32.u64 %0, t; }"
        : "=r"(a) : "l"(p));
    return a;
}

#define CP_ASYNC16(saddr, gptr) \
    asm volatile("cp.async.cg.shared.global [%0], [%1], 16;" \
                 :: "r"(saddr), "l"(gptr) : "memory")
#define CP_COMMIT()  asm volatile("cp.async.commit_group;" ::: "memory")
#define CP_WAIT1()   asm volatile("cp.async.wait_group 1;" ::: "memory")
#define CP_WAIT0()   asm volatile("cp.async.wait_group 0;" ::: "memory")

#define LDMATRIX_X4(r, addr) \
    asm volatile("ldmatrix.sync.aligned.m8n8.x4.shared.b16 {%0,%1,%2,%3}, [%4];" \
        : "=r"((r)[0]), "=r"((r)[1]), "=r"((r)[2]), "=r"((r)[3]) : "r"(addr))

#define MMA_BF16(c, a, b0, b1) \
    asm volatile("mma.sync.aligned.m16n8k16.row.col.f32.bf16.bf16.f32 " \
        "{%0,%1,%2,%3}, {%4,%5,%6,%7}, {%8,%9}, {%0,%1,%2,%3};" \
        : "+f"((c)[0]), "+f"((c)[1]), "+f"((c)[2]), "+f"((c)[3]) \
        : "r"((a)[0]), "r"((a)[1]), "r"((a)[2]), "r"((a)[3]), "r"(b0), "r"(b1))

// ---------------- 1. row L2-normalize + bf16 copy -----------------------------
__global__ void __launch_bounds__(128) normalize_k(const float* __restrict__ feats)
{
    const size_t row = blockIdx.x;
    const float4 v = ((const float4*)(feats + row * DIM))[threadIdx.x];
    float ss = v.x * v.x + v.y * v.y + v.z * v.z + v.w * v.w;
    #pragma unroll
    for (int o = 16; o; o >>= 1) ss += __shfl_xor_sync(0xffffffffu, ss, o);
    __shared__ float s[4];
    if ((threadIdx.x & 31) == 0) s[threadIdx.x >> 5] = ss;
    __syncthreads();
    const float tot = s[0] + s[1] + s[2] + s[3];
    const float inv = 1.0f / fmaxf(sqrtf(tot), 1e-12f);
    float4 o4;
    o4.x = v.x * inv; o4.y = v.y * inv; o4.z = v.z * inv; o4.w = v.w * inv;
    ((float4*)(g_xn + row * DIM))[threadIdx.x] = o4;
    __nv_bfloat162 b0, b1;
    b0.x = __float2bfloat16(o4.x); b0.y = __float2bfloat16(o4.y);
    b1.x = __float2bfloat16(o4.z); b1.y = __float2bfloat16(o4.w);
    ((__nv_bfloat162*)(g_xnb + row * DIM))[threadIdx.x * 2]     = b0;
    ((__nv_bfloat162*)(g_xnb + row * DIM))[threadIdx.x * 2 + 1] = b1;
}

// ---------------- bf16 tensor-core GEMM: C = A * B^T (both K-major) -----------
template <int RELU>
__global__ void __launch_bounds__(256, 2) gemm_bf16_nt(
    const __nv_bfloat16* __restrict__ A, const __nv_bfloat16* __restrict__ B,
    float* __restrict__ C, int N, int K,
    long long strideA, long long strideB, long long strideC)
{
    extern __shared__ char smem_raw[];
    char* tiles = (char*)(((uintptr_t)smem_raw + 1023) & ~(uintptr_t)1023);
    const uint32_t sbase = smem_u32(tiles);

    A += (long long)blockIdx.z * strideA;
    B += (long long)blockIdx.z * strideB;
    C += (long long)blockIdx.z * strideC;

    const int tid  = threadIdx.x;
    const int lane = tid & 31, wid = tid >> 5;
    const int wr = wid >> 2, wc = wid & 3;     // 2 x 4 warp grid
    const int brow = blockIdx.y * 128, bcol = blockIdx.x * 128;

    const int seg = tid & 7;       // 16B segment within 128B row
    const int r0  = tid >> 3;      // 0..31

    const __nv_bfloat16* Ar = A + (size_t)brow * K;
    const __nv_bfloat16* Br = B + (size_t)bcol * K;

    auto load_chunk = [&](int c, int stage) {
        const uint32_t dA = sbase + stage * 32768;
        const uint32_t dB = dA + 16384;
        const size_t koff = (size_t)c * 64 + seg * 8;
        #pragma unroll
        for (int it = 0; it < 4; ++it) {
            const int r = r0 + it * 32;
            uint32_t off = r * 128 + seg * 16;
            off ^= (off >> 3) & 0x70;
            CP_ASYNC16(dA + off, Ar + (size_t)r * K + koff);
            CP_ASYNC16(dB + off, Br + (size_t)r * K + koff);
        }
    };

    float acc[4][4][4];
    #pragma unroll
    for (int mt = 0; mt < 4; ++mt)
        #pragma unroll
        for (int nt = 0; nt < 4; ++nt)
            #pragma unroll
            for (int q = 0; q < 4; ++q) acc[mt][nt][q] = 0.0f;

    const int nk = K >> 6;
    load_chunk(0, 0);
    CP_COMMIT();

    const int mi  = lane >> 3;
    const int l7  = lane & 7;

    #pragma unroll 1
    for (int c = 0; c < nk; ++c) {
        const int st = c & 1;
        if (c + 1 < nk) {
            load_chunk(c + 1, st ^ 1);
            CP_COMMIT();
            CP_WAIT1();
        } else {
            CP_WAIT0();
        }
        __syncthreads();

        const uint32_t tA = sbase + st * 32768;
        const uint32_t tB = tA + 16384;

        #pragma unroll
        for (int ks = 0; ks < 4; ++ks) {
            uint32_t a[4][4], b[2][4];
            #pragma unroll
            for (int mt = 0; mt < 4; ++mt) {
                const int row = wr * 64 + mt * 16 + l7 + ((mi & 1) << 3);
                const int sg  = ks * 2 + (mi >> 1);
                uint32_t off = row * 128 + sg * 16;
                off ^= (off >> 3) & 0x70;
                LDMATRIX_X4(a[mt], tA + off);
            }
            #pragma unroll
            for (int np = 0; np < 2; ++np) {
                const int n  = wc * 32 + np * 16 + l7 + ((mi >> 1) << 3);
                const int sg = ks * 2 + (mi & 1);
                uint32_t off = n * 128 + sg * 16;
                off ^= (off >> 3) & 0x70;
                LDMATRIX_X4(b[np], tB + off);
            }
            #pragma unroll
            for (int mt = 0; mt < 4; ++mt)
                #pragma unroll
                for (int nt = 0; nt < 4; ++nt)
                    MMA_BF16(acc[mt][nt], a[mt],
                             b[nt >> 1][(nt & 1) * 2], b[nt >> 1][(nt & 1) * 2 + 1]);
        }
        __syncthreads();
    }

    // epilogue
    const int rbase = brow + wr * 64 + (lane >> 2);
    const int cbase = bcol + wc * 32 + (lane & 3) * 2;
    #pragma unroll
    for (int mt = 0; mt < 4; ++mt) {
        #pragma unroll
        for (int nt = 0; nt < 4; ++nt) {
            float2 v0, v1;
            v0.x = acc[mt][nt][0]; v0.y = acc[mt][nt][1];
            v1.x = acc[mt][nt][2]; v1.y = acc[mt][nt][3];
            if (RELU) {
                v0.x = fmaxf(v0.x, 0.f); v0.y = fmaxf(v0.y, 0.f);
                v1.x = fmaxf(v1.x, 0.f); v1.y = fmaxf(v1.y, 0.f);
            }
            const int row = rbase + mt * 16;
            const int col = cbase + nt * 8;
            *(float2*)(C + (size_t)row * N + col)       = v0;
            *(float2*)(C + (size_t)(row + 8) * N + col) = v1;
        }
    }
}

// ---------------- ordering helpers (jax.lax.top_k: desc value, tie -> low idx) -
__device__ __forceinline__ bool pref(float v, int i, float v2, int i2)
{
    return (v > v2) || (v == v2 && i < i2);
}

__device__ __forceinline__ void ins3(float v, int i, float tv[3], int ti[3])
{
    if (!pref(v, i, tv[2], ti[2])) return;
    tv[2] = v; ti[2] = i;
    if (pref(tv[2], ti[2], tv[1], ti[1])) {
        float fv = tv[1]; int fi = ti[1];
        tv[1] = tv[2]; ti[1] = ti[2]; tv[2] = fv; ti[2] = fi;
    }
    if (pref(tv[1], ti[1], tv[0], ti[0])) {
        float fv = tv[0]; int fi = ti[0];
        tv[0] = tv[1]; ti[0] = ti[1]; tv[1] = fv; ti[1] = fi;
    }
}

// ---------------- 3a. top-8 candidates per row, warp-per-row, packed u64 ------
// key = (monotone(valbits) << 32) | ~idx  -> single u64 compare implements
// (desc value, tie -> lower index). Exactly the top-8 of the stored scores.
// All per-lane state uses STATIC indexing only (no spills).
__device__ __forceinline__ unsigned long long pack_key(float v, int idx)
{
    uint32_t u = __float_as_uint(v);
    u = (u & 0x80000000u) ? ~u : (u | 0x80000000u);
    return ((unsigned long long)u << 32) | (uint32_t)(~idx);
}

__device__ __forceinline__ void sins8(unsigned long long k, unsigned long long t[8])
{
    if (k > t[7]) {
        t[7] = k;
        #pragma unroll
        for (int e = 7; e > 0; --e) {
            if (t[e] > t[e - 1]) {
                unsigned long long tmp = t[e - 1];
                t[e - 1] = t[e]; t[e] = tmp;
            }
        }
    }
}

__global__ void __launch_bounds__(256) top8_k(void)
{
    const int row  = blockIdx.x * 8 + (threadIdx.x >> 5);
    const int lane = threadIdx.x & 31;
    const float4* d = (const float4*)(g_dis + (size_t)row * NPTS);

    unsigned long long t[8];
    #pragma unroll
    for (int e = 0; e < 8; ++e) t[e] = 0ull;

    #pragma unroll 2
    for (int it = 0; it < 16; ++it) {
        const int f4 = it * 32 + lane;
        const float4 v = d[f4];
        const int base = f4 * 4;
        sins8(pack_key(v.x, base + 0), t);
        sins8(pack_key(v.y, base + 1), t);
        sins8(pack_key(v.z, base + 2), t);
        sins8(pack_key(v.w, base + 3), t);
    }

    // merge 32 sorted lists: 8 rounds of warp-max over the list HEADS (t[0]
    // is always the live candidate -> static index), winner shifts left.
    int out[8];
    #pragma unroll
    for (int r = 0; r < 8; ++r) {
        unsigned long long m = t[0];
        #pragma unroll
        for (int o = 16; o; o >>= 1) {
            unsigned long long other = __shfl_xor_sync(0xffffffffu, m, o);
            if (other > m) m = other;
        }
        if (t[0] == m) {   // unique keys: exactly one lane pops its head
            t[0] = t[1]; t[1] = t[2]; t[2] = t[3]; t[3] = t[4];
            t[4] = t[5]; t[5] = t[6]; t[6] = t[7]; t[7] = 0ull;
        }
        out[r] = ~(uint32_t)m;
    }
    if (lane == 0) {
        #pragma unroll
        for (int e = 0; e < 8; ++e) g_idx8[(size_t)row * 8 + e] = out[e];
    }
}

// ---------------- 3b. exact fp32 rescore of the 8 candidates, pick top-3 ------
__global__ void __launch_bounds__(256) rescore_k(void)
{
    const int gw   = blockIdx.x * 8 + (threadIdx.x >> 5);   // row, 1 warp/row
    const int lane = threadIdx.x & 31;
    const int b    = gw >> 11;

    const float4* xrow = (const float4*)(g_xn + (size_t)gw * DIM);
    float4 x[4];
    #pragma unroll
    for (int q = 0; q < 4; ++q) x[q] = xrow[q * 32 + lane];

    float bv[3] = { -1e30f, -1e30f, -1e30f };
    int   bi[3] = { 0x7fffffff, 0x7fffffff, 0x7fffffff };

    #pragma unroll
    for (int c = 0; c < 8; ++c) {
        const int cand = g_idx8[(size_t)gw * 8 + c];
        const float4* yr = (const float4*)(g_xn + ((size_t)(b << 11) + cand) * DIM);
        float s = 0.0f;
        #pragma unroll
        for (int q = 0; q < 4; ++q) {
            const float4 y = yr[q * 32 + lane];
            s += x[q].x * y.x + x[q].y * y.y + x[q].z * y.z + x[q].w * y.w;
        }
        #pragma unroll
        for (int o = 16; o; o >>= 1) s += __shfl_xor_sync(0xffffffffu, s, o);
        ins3(s, cand, bv, bi);
    }
    if (lane == 0) {
        g_idx[gw * 3 + 0] = bi[0];
        g_idx[gw * 3 + 1] = bi[1];
        g_idx[gw * 3 + 2] = bi[2];
    }
}

// ---------------- 4. gather + conv-mapping + softmax + mean-pool --------------
__global__ void __launch_bounds__(256) conv_pool2_k(
    const float* __restrict__ feats,
    const float* __restrict__ convw,   // (3,3,512)
    const float* __restrict__ convb)   // (3,3)
{
    __shared__ float wsm[9 * DIM];      // 18 KB
    const int tid = threadIdx.x, lane = tid & 31, wid = tid >> 5;

    for (int i = tid; i < 9 * DIM / 4; i += 256)
        ((float4*)wsm)[i] = ((const float4*)convw)[i];
    __syncthreads();

    const int node = blockIdx.x * 8 + wid;
    const int b = node >> 11;
    const float* fb = feats + (size_t)b * NPTS * DIM;

    float4 kr[3][4];
    #pragma unroll
    for (int g = 0; g < 3; ++g) {
        const int id = g_idx[(size_t)node * 3 + g];
        const float4* yp = (const float4*)(fb + (size_t)id * DIM);
        #pragma unroll
        for (int q = 0; q < 4; ++q) kr[g][q] = yp[q * 32 + lane];
    }

    float p[9];
    #pragma unroll
    for (int q9 = 0; q9 < 9; ++q9) p[q9] = 0.0f;
    #pragma unroll
    for (int q = 0; q < 4; ++q) {
        const int col4 = q * 32 + lane;
        #pragma unroll
        for (int g = 0; g < 3; ++g) {
            const float4 kv = kr[g][q];
            #pragma unroll
            for (int j = 0; j < 3; ++j) {
                const float4 wv = ((const float4*)wsm)[(g * 3 + j) * 128 + col4];
                p[g * 3 + j] += kv.x * wv.x + kv.y * wv.y + kv.z * wv.z + kv.w * wv.w;
            }
        }
    }
    #pragma unroll
    for (int q9 = 0; q9 < 9; ++q9)
        #pragma unroll
        for (int o = 16; o; o >>= 1) p[q9] += __shfl_xor_sync(0xffffffffu, p[q9], o);

    float w0 = 0.f, w1 = 0.f, w2 = 0.f;
    #pragma unroll
    for (int g = 0; g < 3; ++g) {
        const float m0 = p[g * 3 + 0] + __ldg(convb + g * 3 + 0);
        const float m1 = p[g * 3 + 1] + __ldg(convb + g * 3 + 1);
        const float m2 = p[g * 3 + 2] + __ldg(convb + g * 3 + 2);
        const float mx = fmaxf(m0, fmaxf(m1, m2));
        const float e0 = expf(m0 - mx), e1 = expf(m1 - mx), e2 = expf(m2 - mx);
        const float inv = 1.0f / (e0 + e1 + e2);
        w0 += e0 * inv; w1 += e1 * inv; w2 += e2 * inv;
    }
    const float third = 1.0f / 3.0f;
    const float c0 = w0 * third, c1 = w1 * third, c2 = w2 * third;

    float* op = g_pooled + (size_t)node * DIM;
    #pragma unroll
    for (int q = 0; q < 4; ++q) {
        float4 o;
        o.x = c0 * kr[0][q].x + c1 * kr[1][q].x + c2 * kr[2][q].x;
        o.y = c0 * kr[0][q].y + c1 * kr[1][q].y + c2 * kr[2][q].y;
        o.z = c0 * kr[0][q].z + c1 * kr[1][q].z + c2 * kr[2][q].z;
        o.w = c0 * kr[0][q].w + c1 * kr[1][q].w + c2 * kr[2][q].w;
        ((float4*)op)[q * 32 + lane] = o;
    }
}

// ---------------- split fp32 -> [hi, hi, lo] / [hi, lo, hi] bf16 ---------------
__device__ __forceinline__ void split4(const float4 v,
                                       __nv_bfloat162& h01, __nv_bfloat162& h23,
                                       __nv_bfloat162& l01, __nv_bfloat162& l23)
{
    const __nv_bfloat16 h0 = __float2bfloat16(v.x);
    const __nv_bfloat16 h1 = __float2bfloat16(v.y);
    const __nv_bfloat16 h2 = __float2bfloat16(v.z);
    const __nv_bfloat16 h3 = __float2bfloat16(v.w);
    h01.x = h0; h01.y = h1; h23.x = h2; h23.y = h3;
    l01.x = __float2bfloat16(v.x - __bfloat162float(h0));
    l01.y = __float2bfloat16(v.y - __bfloat162float(h1));
    l23.x = __float2bfloat16(v.z - __bfloat162float(h2));
    l23.y = __float2bfloat16(v.w - __bfloat162float(h3));
}

__global__ void __launch_bounds__(128) splitA_k(void)
{
    const size_t row = blockIdx.x;
    const int c = threadIdx.x * 4;
    const float4 v = ((const float4*)(g_pooled + row * DIM))[threadIdx.x];
    __nv_bfloat162 h01, h23, l01, l23;
    split4(v, h01, h23, l01, l23);
    __nv_bfloat162* dst = (__nv_bfloat162*)(g_fcA + row * FCK);
    dst[(c) / 2]          = h01; dst[(c) / 2 + 1]          = h23;  // [0,512): hi
    dst[(c + 512) / 2]    = h01; dst[(c + 512) / 2 + 1]    = h23;  // [512,1024): hi
    dst[(c + 1024) / 2]   = l01; dst[(c + 1024) / 2 + 1]   = l23;  // [1024,1536): lo
}

__global__ void __launch_bounds__(128) splitB_k(const float* __restrict__ fcw)
{
    const size_t row = blockIdx.x;
    const int c = threadIdx.x * 4;
    const float4 v = ((const float4*)(fcw + row * DIM))[threadIdx.x];
    __nv_bfloat162 h01, h23, l01, l23;
    split4(v, h01, h23, l01, l23);
    __nv_bfloat162* dst = (__nv_bfloat162*)(g_fcB + row * FCK);
    dst[(c) / 2]          = h01; dst[(c) / 2 + 1]          = h23;  // [0,512): hi
    dst[(c + 512) / 2]    = l01; dst[(c + 512) / 2 + 1]    = l23;  // [512,1024): lo
    dst[(c + 1024) / 2]   = h01; dst[(c + 1024) / 2 + 1]   = h23;  // [1024,1536): hi
}

// ---------------- launch -------------------------------------------------------
extern "C" void kernel_launch(void* const* d_in, const int* in_sizes, int n_in,
                              void* d_out, int out_size)
{
    const float* feats = (const float*)d_in[0];
    const float* convw = (const float*)d_in[1];
    const float* convb = (const float*)d_in[2];
    const float* fcw   = (const float*)d_in[3];
    float* out = (float*)d_out;

    void *xnb_p, *dis_p, *fcA_p, *fcB_p;
    cudaGetSymbolAddress(&xnb_p, g_xnb);
    cudaGetSymbolAddress(&dis_p, g_dis);
    cudaGetSymbolAddress(&fcA_p, g_fcA);
    cudaGetSymbolAddress(&fcB_p, g_fcB);

    const int smem_bytes = 66 * 1024;
    cudaFuncSetAttribute(gemm_bf16_nt<0>,
                         cudaFuncAttributeMaxDynamicSharedMemorySize, smem_bytes);
    cudaFuncSetAttribute(gemm_bf16_nt<1>,
                         cudaFuncAttributeMaxDynamicSharedMemorySize, smem_bytes);

    // 1. normalize rows (fp32 + bf16 copies)
    normalize_k<<<NROWS, 128>>>(feats);

    // split fc weights early (independent)
    splitB_k<<<DIM, 128>>>(fcw);

    // 2. cosine similarity: bf16 mma.sync, fp32 accumulate
    {
        dim3 grid(NPTS / 128, NPTS / 128, BATCH);
        gemm_bf16_nt<0><<<grid, 256, smem_bytes>>>(
            (const __nv_bfloat16*)xnb_p, (const __nv_bfloat16*)xnb_p, (float*)dis_p,
            NPTS, DIM,
            (long long)NPTS * DIM, (long long)NPTS * DIM, (long long)NPTS * NPTS);
    }

    // 3. top-8 candidates (warp per row), then exact fp32 rescore -> top-3
    top8_k<<<NROWS / 8, 256>>>();
    rescore_k<<<NROWS / 8, 256>>>();

    // 4. gather + conv mapping + softmax + pool (warp per node)
    conv_pool2_k<<<NROWS / 8, 256>>>(feats, convw, convb);

    // 5. fc + relu: split-precision bf16 GEMM, K=1536
    splitA_k<<<NROWS, 128>>>();
    {
        dim3 grid(DIM / 128, NROWS / 128, 1);
        gemm_bf16_nt<1><<<grid, 256, smem_bytes>>>(
            (const __nv_bfloat16*)fcA_p, (const __nv_bfloat16*)fcB_p, out,
            DIM, FCK, 0, 0, 0);
    }
}

// round 6
// speedup vs baseline: 3.3671x; 1.3252x over previous
#include <cuda_runtime.h>
#include <cuda_bf16.h>
#include <math.h>
#include <stdint.h>

// Problem constants (fixed by the dataset)
#define BATCH 8
#define NPTS  2048
#define DIM   512
#define KN    3
#define NROWS (BATCH * NPTS)   // 16384
#define FCK   1536             // split-precision fc: 3 * DIM

// ---------------- scratch (static device memory; no allocs allowed) ----------
__device__ float         g_xn [(size_t)NROWS * DIM];            // 32 MB fp32 normalized
__device__ __nv_bfloat16 g_xnb[(size_t)NROWS * DIM];            // 16 MB bf16 normalized
__device__ float         g_dis[(size_t)BATCH * NPTS * NPTS];    // 134 MB scores
__device__ int           g_idx8[(size_t)NROWS * 8];
__device__ int           g_idx [(size_t)NROWS * KN];
__device__ __nv_bfloat16 g_fcA[(size_t)NROWS * FCK];            // 48 MB  [hi, hi, lo]
__device__ __nv_bfloat16 g_fcB[(size_t)DIM * FCK];              // 1.5 MB [hi, lo, hi]

// ============================ PTX helpers ======================================
__device__ __forceinline__ uint32_t smem_u32(const void* p) {
    uint32_t a;
    asm("{ .reg .u64 t; cvta.to.shared.u64 t, %1; cvt.u32.u64 %0, t; }"
        : "=r"(a) : "l"(p));
    return a;
}

#define CP_ASYNC16(saddr, gptr) \
    asm volatile("cp.async.cg.shared.global [%0], [%1], 16;" \
                 :: "r"(saddr), "l"(gptr) : "memory")
#define CP_COMMIT()  asm volatile("cp.async.commit_group;" ::: "memory")
#define CP_WAIT1()   asm volatile("cp.async.wait_group 1;" ::: "memory")
#define CP_WAIT0()   asm volatile("cp.async.wait_group 0;" ::: "memory")

#define LDMATRIX_X4(r, addr) \
    asm volatile("ldmatrix.sync.aligned.m8n8.x4.shared.b16 {%0,%1,%2,%3}, [%4];" \
        : "=r"((r)[0]), "=r"((r)[1]), "=r"((r)[2]), "=r"((r)[3]) : "r"(addr))

#define MMA_BF16(c, a, b0, b1) \
    asm volatile("mma.sync.aligned.m16n8k16.row.col.f32.bf16.bf16.f32 " \
        "{%0,%1,%2,%3}, {%4,%5,%6,%7}, {%8,%9}, {%0,%1,%2,%3};" \
        : "+f"((c)[0]), "+f"((c)[1]), "+f"((c)[2]), "+f"((c)[3]) \
        : "r"((a)[0]), "r"((a)[1]), "r"((a)[2]), "r"((a)[3]), "r"(b0), "r"(b1))

// ---------------- 1. row L2-normalize + bf16 copy -----------------------------
__global__ void __launch_bounds__(128) normalize_k(const float* __restrict__ feats)
{
    const size_t row = blockIdx.x;
    const float4 v = ((const float4*)(feats + row * DIM))[threadIdx.x];
    float ss = v.x * v.x + v.y * v.y + v.z * v.z + v.w * v.w;
    #pragma unroll
    for (int o = 16; o; o >>= 1) ss += __shfl_xor_sync(0xffffffffu, ss, o);
    __shared__ float s[4];
    if ((threadIdx.x & 31) == 0) s[threadIdx.x >> 5] = ss;
    __syncthreads();
    const float tot = s[0] + s[1] + s[2] + s[3];
    const float inv = 1.0f / fmaxf(sqrtf(tot), 1e-12f);
    float4 o4;
    o4.x = v.x * inv; o4.y = v.y * inv; o4.z = v.z * inv; o4.w = v.w * inv;
    ((float4*)(g_xn + row * DIM))[threadIdx.x] = o4;
    __nv_bfloat162 b0, b1;
    b0.x = __float2bfloat16(o4.x); b0.y = __float2bfloat16(o4.y);
    b1.x = __float2bfloat16(o4.z); b1.y = __float2bfloat16(o4.w);
    ((__nv_bfloat162*)(g_xnb + row * DIM))[threadIdx.x * 2]     = b0;
    ((__nv_bfloat162*)(g_xnb + row * DIM))[threadIdx.x * 2 + 1] = b1;
}

// ---------------- bf16 tensor-core GEMM: C = A * B^T (both K-major) -----------
template <int RELU>
__global__ void __launch_bounds__(256, 2) gemm_bf16_nt(
    const __nv_bfloat16* __restrict__ A, const __nv_bfloat16* __restrict__ B,
    float* __restrict__ C, int N, int K,
    long long strideA, long long strideB, long long strideC)
{
    extern __shared__ char smem_raw[];
    char* tiles = (char*)(((uintptr_t)smem_raw + 1023) & ~(uintptr_t)1023);
    const uint32_t sbase = smem_u32(tiles);

    A += (long long)blockIdx.z * strideA;
    B += (long long)blockIdx.z * strideB;
    C += (long long)blockIdx.z * strideC;

    const int tid  = threadIdx.x;
    const int lane = tid & 31, wid = tid >> 5;
    const int wr = wid >> 2, wc = wid & 3;     // 2 x 4 warp grid
    const int brow = blockIdx.y * 128, bcol = blockIdx.x * 128;

    const int seg = tid & 7;       // 16B segment within 128B row
    const int r0  = tid >> 3;      // 0..31

    const __nv_bfloat16* Ar = A + (size_t)brow * K;
    const __nv_bfloat16* Br = B + (size_t)bcol * K;

    auto load_chunk = [&](int c, int stage) {
        const uint32_t dA = sbase + stage * 32768;
        const uint32_t dB = dA + 16384;
        const size_t koff = (size_t)c * 64 + seg * 8;
        #pragma unroll
        for (int it = 0; it < 4; ++it) {
            const int r = r0 + it * 32;
            uint32_t off = r * 128 + seg * 16;
            off ^= (off >> 3) & 0x70;
            CP_ASYNC16(dA + off, Ar + (size_t)r * K + koff);
            CP_ASYNC16(dB + off, Br + (size_t)r * K + koff);
        }
    };

    float acc[4][4][4];
    #pragma unroll
    for (int mt = 0; mt < 4; ++mt)
        #pragma unroll
        for (int nt = 0; nt < 4; ++nt)
            #pragma unroll
            for (int q = 0; q < 4; ++q) acc[mt][nt][q] = 0.0f;

    const int nk = K >> 6;
    load_chunk(0, 0);
    CP_COMMIT();

    const int mi  = lane >> 3;
    const int l7  = lane & 7;

    #pragma unroll 1
    for (int c = 0; c < nk; ++c) {
        const int st = c & 1;
        if (c + 1 < nk) {
            load_chunk(c + 1, st ^ 1);
            CP_COMMIT();
            CP_WAIT1();
        } else {
            CP_WAIT0();
        }
        __syncthreads();

        const uint32_t tA = sbase + st * 32768;
        const uint32_t tB = tA + 16384;

        #pragma unroll
        for (int ks = 0; ks < 4; ++ks) {
            uint32_t a[4][4], b[2][4];
            #pragma unroll
            for (int mt = 0; mt < 4; ++mt) {
                const int row = wr * 64 + mt * 16 + l7 + ((mi & 1) << 3);
                const int sg  = ks * 2 + (mi >> 1);
                uint32_t off = row * 128 + sg * 16;
                off ^= (off >> 3) & 0x70;
                LDMATRIX_X4(a[mt], tA + off);
            }
            #pragma unroll
            for (int np = 0; np < 2; ++np) {
                const int n  = wc * 32 + np * 16 + l7 + ((mi >> 1) << 3);
                const int sg = ks * 2 + (mi & 1);
                uint32_t off = n * 128 + sg * 16;
                off ^= (off >> 3) & 0x70;
                LDMATRIX_X4(b[np], tB + off);
            }
            #pragma unroll
            for (int mt = 0; mt < 4; ++mt)
                #pragma unroll
                for (int nt = 0; nt < 4; ++nt)
                    MMA_BF16(acc[mt][nt], a[mt],
                             b[nt >> 1][(nt & 1) * 2], b[nt >> 1][(nt & 1) * 2 + 1]);
        }
        __syncthreads();
    }

    // epilogue
    const int rbase = brow + wr * 64 + (lane >> 2);
    const int cbase = bcol + wc * 32 + (lane & 3) * 2;
    #pragma unroll
    for (int mt = 0; mt < 4; ++mt) {
        #pragma unroll
        for (int nt = 0; nt < 4; ++nt) {
            float2 v0, v1;
            v0.x = acc[mt][nt][0]; v0.y = acc[mt][nt][1];
            v1.x = acc[mt][nt][2]; v1.y = acc[mt][nt][3];
            if (RELU) {
                v0.x = fmaxf(v0.x, 0.f); v0.y = fmaxf(v0.y, 0.f);
                v1.x = fmaxf(v1.x, 0.f); v1.y = fmaxf(v1.y, 0.f);
            }
            const int row = rbase + mt * 16;
            const int col = cbase + nt * 8;
            *(float2*)(C + (size_t)row * N + col)       = v0;
            *(float2*)(C + (size_t)(row + 8) * N + col) = v1;
        }
    }
}

// ---------------- ordering helpers (jax.lax.top_k: desc value, tie -> low idx) -
__device__ __forceinline__ bool pref(float v, int i, float v2, int i2)
{
    return (v > v2) || (v == v2 && i < i2);
}

__device__ __forceinline__ void ins3(float v, int i, float tv[3], int ti[3])
{
    if (!pref(v, i, tv[2], ti[2])) return;
    tv[2] = v; ti[2] = i;
    if (pref(tv[2], ti[2], tv[1], ti[1])) {
        float fv = tv[1]; int fi = ti[1];
        tv[1] = tv[2]; ti[1] = ti[2]; tv[2] = fv; ti[2] = fi;
    }
    if (pref(tv[1], ti[1], tv[0], ti[0])) {
        float fv = tv[0]; int fi = ti[0];
        tv[0] = tv[1]; ti[0] = ti[1]; tv[1] = fv; ti[1] = fi;
    }
}

// ---------------- 3a. top-8 per row: threshold-filtered two-pass ---------------
// Pass 1: lane max over 64 elems; warp computes T = 8th-largest of the 32 lane
// maxima. Since the 8th order statistic of a subset <= that of the full row,
// "v >= T" provably keeps the entire true top-8 (and >= 8 elements pass).
// Pass 2: rescan (L1/L2-hot), only survivors do the u64 pack + sorted insert.
__device__ __forceinline__ unsigned long long pack_key(float v, int idx)
{
    uint32_t u = __float_as_uint(v);
    u = (u & 0x80000000u) ? ~u : (u | 0x80000000u);
    return ((unsigned long long)u << 32) | (uint32_t)(~idx);
}

__device__ __forceinline__ void sins8(unsigned long long k, unsigned long long t[8])
{
    if (k > t[7]) {
        t[7] = k;
        #pragma unroll
        for (int e = 7; e > 0; --e) {
            if (t[e] > t[e - 1]) {
                unsigned long long tmp = t[e - 1];
                t[e - 1] = t[e]; t[e] = tmp;
            }
        }
    }
}

__global__ void __launch_bounds__(256) top8_k(void)
{
    const int row  = blockIdx.x * 8 + (threadIdx.x >> 5);
    const int lane = threadIdx.x & 31;
    const float4* d = (const float4*)(g_dis + (size_t)row * NPTS);

    // ---- pass 1: per-lane max ----
    float mx = -1e30f;
    #pragma unroll
    for (int it = 0; it < 16; ++it) {
        const float4 v = d[it * 32 + lane];
        mx = fmaxf(mx, fmaxf(fmaxf(v.x, v.y), fmaxf(v.z, v.w)));
    }

    // warp: 8th largest of the 32 lane maxima (monotone u32 space)
    uint32_t xu = __float_as_uint(mx);
    xu = (xu & 0x80000000u) ? ~xu : (xu | 0x80000000u);
    uint32_t live = xu, T = 0;
    #pragma unroll
    for (int r = 0; r < 8; ++r) {
        uint32_t m = live;
        #pragma unroll
        for (int o = 16; o; o >>= 1) {
            uint32_t oth = __shfl_xor_sync(0xffffffffu, m, o);
            if (oth > m) m = oth;
        }
        if (live == m) live = 0;
        T = m;
    }
    // back to fp32 threshold
    const uint32_t Tx = (T & 0x80000000u) ? (T ^ 0x80000000u) : ~T;
    const float Tf = __uint_as_float(Tx);

    // ---- pass 2: filtered exact top-8 ----
    unsigned long long t[8];
    #pragma unroll
    for (int e = 0; e < 8; ++e) t[e] = 0ull;

    #pragma unroll 2
    for (int it = 0; it < 16; ++it) {
        const int f4 = it * 32 + lane;
        const float4 v = d[f4];
        const int base = f4 * 4;
        if (v.x >= Tf) sins8(pack_key(v.x, base + 0), t);
        if (v.y >= Tf) sins8(pack_key(v.y, base + 1), t);
        if (v.z >= Tf) sins8(pack_key(v.z, base + 2), t);
        if (v.w >= Tf) sins8(pack_key(v.w, base + 3), t);
    }

    // merge 32 sorted lists: 8 rounds of warp-max over heads, winner shifts.
    int out[8];
    #pragma unroll
    for (int r = 0; r < 8; ++r) {
        unsigned long long m = t[0];
        #pragma unroll
        for (int o = 16; o; o >>= 1) {
            unsigned long long other = __shfl_xor_sync(0xffffffffu, m, o);
            if (other > m) m = other;
        }
        if (t[0] == m) {   // unique keys: exactly one lane pops its head
            t[0] = t[1]; t[1] = t[2]; t[2] = t[3]; t[3] = t[4];
            t[4] = t[5]; t[5] = t[6]; t[6] = t[7]; t[7] = 0ull;
        }
        out[r] = ~(uint32_t)m;
    }
    if (lane == 0) {
        #pragma unroll
        for (int e = 0; e < 8; ++e) g_idx8[(size_t)row * 8 + e] = out[e];
    }
}

// ---------------- 3b. exact fp32 rescore of the 8 candidates, pick top-3 ------
__global__ void __launch_bounds__(256) rescore_k(void)
{
    const int gw   = blockIdx.x * 8 + (threadIdx.x >> 5);   // row, 1 warp/row
    const int lane = threadIdx.x & 31;
    const int b    = gw >> 11;

    const float4* xrow = (const float4*)(g_xn + (size_t)gw * DIM);
    float4 x[4];
    #pragma unroll
    for (int q = 0; q < 4; ++q) x[q] = xrow[q * 32 + lane];

    float bv[3] = { -1e30f, -1e30f, -1e30f };
    int   bi[3] = { 0x7fffffff, 0x7fffffff, 0x7fffffff };

    #pragma unroll
    for (int c = 0; c < 8; ++c) {
        const int cand = g_idx8[(size_t)gw * 8 + c];
        const float4* yr = (const float4*)(g_xn + ((size_t)(b << 11) + cand) * DIM);
        float s = 0.0f;
        #pragma unroll
        for (int q = 0; q < 4; ++q) {
            const float4 y = yr[q * 32 + lane];
            s += x[q].x * y.x + x[q].y * y.y + x[q].z * y.z + x[q].w * y.w;
        }
        #pragma unroll
        for (int o = 16; o; o >>= 1) s += __shfl_xor_sync(0xffffffffu, s, o);
        ins3(s, cand, bv, bi);
    }
    if (lane == 0) {
        g_idx[gw * 3 + 0] = bi[0];
        g_idx[gw * 3 + 1] = bi[1];
        g_idx[gw * 3 + 2] = bi[2];
    }
}

// ---------------- 4. gather + conv-mapping + softmax + pool + fcA split -------
// warp-per-node; writes hi/hi/lo bf16 decomposition of pooled directly to g_fcA.
__global__ void __launch_bounds__(256) conv_pool2_k(
    const float* __restrict__ feats,
    const float* __restrict__ convw,   // (3,3,512)
    const float* __restrict__ convb)   // (3,3)
{
    __shared__ float wsm[9 * DIM];      // 18 KB
    const int tid = threadIdx.x, lane = tid & 31, wid = tid >> 5;

    for (int i = tid; i < 9 * DIM / 4; i += 256)
        ((float4*)wsm)[i] = ((const float4*)convw)[i];
    __syncthreads();

    const int node = blockIdx.x * 8 + wid;
    const int b = node >> 11;
    const float* fb = feats + (size_t)b * NPTS * DIM;

    float4 kr[3][4];
    #pragma unroll
    for (int g = 0; g < 3; ++g) {
        const int id = g_idx[(size_t)node * 3 + g];
        const float4* yp = (const float4*)(fb + (size_t)id * DIM);
        #pragma unroll
        for (int q = 0; q < 4; ++q) kr[g][q] = yp[q * 32 + lane];
    }

    float p[9];
    #pragma unroll
    for (int q9 = 0; q9 < 9; ++q9) p[q9] = 0.0f;
    #pragma unroll
    for (int q = 0; q < 4; ++q) {
        const int col4 = q * 32 + lane;
        #pragma unroll
        for (int g = 0; g < 3; ++g) {
            const float4 kv = kr[g][q];
            #pragma unroll
            for (int j = 0; j < 3; ++j) {
                const float4 wv = ((const float4*)wsm)[(g * 3 + j) * 128 + col4];
                p[g * 3 + j] += kv.x * wv.x + kv.y * wv.y + kv.z * wv.z + kv.w * wv.w;
            }
        }
    }
    #pragma unroll
    for (int q9 = 0; q9 < 9; ++q9)
        #pragma unroll
        for (int o = 16; o; o >>= 1) p[q9] += __shfl_xor_sync(0xffffffffu, p[q9], o);

    float w0 = 0.f, w1 = 0.f, w2 = 0.f;
    #pragma unroll
    for (int g = 0; g < 3; ++g) {
        const float m0 = p[g * 3 + 0] + __ldg(convb + g * 3 + 0);
        const float m1 = p[g * 3 + 1] + __ldg(convb + g * 3 + 1);
        const float m2 = p[g * 3 + 2] + __ldg(convb + g * 3 + 2);
        const float mx = fmaxf(m0, fmaxf(m1, m2));
        const float e0 = expf(m0 - mx), e1 = expf(m1 - mx), e2 = expf(m2 - mx);
        const float inv = 1.0f / (e0 + e1 + e2);
        w0 += e0 * inv; w1 += e1 * inv; w2 += e2 * inv;
    }
    const float third = 1.0f / 3.0f;
    const float c0 = w0 * third, c1 = w1 * third, c2 = w2 * third;

    __nv_bfloat16* ap = g_fcA + (size_t)node * FCK;
    #pragma unroll
    for (int q = 0; q < 4; ++q) {
        float4 o;
        o.x = c0 * kr[0][q].x + c1 * kr[1][q].x + c2 * kr[2][q].x;
        o.y = c0 * kr[0][q].y + c1 * kr[1][q].y + c2 * kr[2][q].y;
        o.z = c0 * kr[0][q].z + c1 * kr[1][q].z + c2 * kr[2][q].z;
        o.w = c0 * kr[0][q].w + c1 * kr[1][q].w + c2 * kr[2][q].w;
        // split into hi (bf16) + lo (bf16 of residual)
        __nv_bfloat162 h01, h23, l01, l23;
        h01.x = __float2bfloat16(o.x); h01.y = __float2bfloat16(o.y);
        h23.x = __float2bfloat16(o.z); h23.y = __float2bfloat16(o.w);
        l01.x = __float2bfloat16(o.x - __bfloat162float(h01.x));
        l01.y = __float2bfloat16(o.y - __bfloat162float(h01.y));
        l23.x = __float2bfloat16(o.z - __bfloat162float(h23.x));
        l23.y = __float2bfloat16(o.w - __bfloat162float(h23.y));
        const int c = (q * 32 + lane) * 4;
        __nv_bfloat162* dst = (__nv_bfloat162*)ap;
        dst[c / 2]              = h01; dst[c / 2 + 1]              = h23; // hi
        dst[(c + 512) / 2]      = h01; dst[(c + 512) / 2 + 1]      = h23; // hi
        dst[(c + 1024) / 2]     = l01; dst[(c + 1024) / 2 + 1]     = l23; // lo
    }
}

// ---------------- split fc weights: [hi, lo, hi] -------------------------------
__global__ void __launch_bounds__(128) splitB_k(const float* __restrict__ fcw)
{
    const size_t row = blockIdx.x;
    const int c = threadIdx.x * 4;
    const float4 v = ((const float4*)(fcw + row * DIM))[threadIdx.x];
    __nv_bfloat162 h01, h23, l01, l23;
    h01.x = __float2bfloat16(v.x); h01.y = __float2bfloat16(v.y);
    h23.x = __float2bfloat16(v.z); h23.y = __float2bfloat16(v.w);
    l01.x = __float2bfloat16(v.x - __bfloat162float(h01.x));
    l01.y = __float2bfloat16(v.y - __bfloat162float(h01.y));
    l23.x = __float2bfloat16(v.z - __bfloat162float(h23.x));
    l23.y = __float2bfloat16(v.w - __bfloat162float(h23.y));
    __nv_bfloat162* dst = (__nv_bfloat162*)(g_fcB + row * FCK);
    dst[c / 2]            = h01; dst[c / 2 + 1]            = h23;  // hi
    dst[(c + 512) / 2]    = l01; dst[(c + 512) / 2 + 1]    = l23;  // lo
    dst[(c + 1024) / 2]   = h01; dst[(c + 1024) / 2 + 1]   = h23;  // hi
}

// ---------------- launch -------------------------------------------------------
extern "C" void kernel_launch(void* const* d_in, const int* in_sizes, int n_in,
                              void* d_out, int out_size)
{
    const float* feats = (const float*)d_in[0];
    const float* convw = (const float*)d_in[1];
    const float* convb = (const float*)d_in[2];
    const float* fcw   = (const float*)d_in[3];
    float* out = (float*)d_out;

    void *xnb_p, *dis_p, *fcA_p, *fcB_p;
    cudaGetSymbolAddress(&xnb_p, g_xnb);
    cudaGetSymbolAddress(&dis_p, g_dis);
    cudaGetSymbolAddress(&fcA_p, g_fcA);
    cudaGetSymbolAddress(&fcB_p, g_fcB);

    const int smem_bytes = 66 * 1024;
    cudaFuncSetAttribute(gemm_bf16_nt<0>,
                         cudaFuncAttributeMaxDynamicSharedMemorySize, smem_bytes);
    cudaFuncSetAttribute(gemm_bf16_nt<1>,
                         cudaFuncAttributeMaxDynamicSharedMemorySize, smem_bytes);

    // 1. normalize rows (fp32 + bf16 copies)
    normalize_k<<<NROWS, 128>>>(feats);

    // split fc weights early (independent)
    splitB_k<<<DIM, 128>>>(fcw);

    // 2. cosine similarity: bf16 mma.sync, fp32 accumulate
    {
        dim3 grid(NPTS / 128, NPTS / 128, BATCH);
        gemm_bf16_nt<0><<<grid, 256, smem_bytes>>>(
            (const __nv_bfloat16*)xnb_p, (const __nv_bfloat16*)xnb_p, (float*)dis_p,
            NPTS, DIM,
            (long long)NPTS * DIM, (long long)NPTS * DIM, (long long)NPTS * NPTS);
    }

    // 3. top-8 candidates (threshold two-pass), exact fp32 rescore -> top-3
    top8_k<<<NROWS / 8, 256>>>();
    rescore_k<<<NROWS / 8, 256>>>();

    // 4. gather + conv mapping + softmax + pool, fused hi/lo split into g_fcA
    conv_pool2_k<<<NROWS / 8, 256>>>(feats, convw, convb);

    // 5. fc + relu: split-precision bf16 GEMM, K=1536
    {
        dim3 grid(DIM / 128, NROWS / 128, 1);
        gemm_bf16_nt<1><<<grid, 256, smem_bytes>>>(
            (const __nv_bfloat16*)fcA_p, (const __nv_bfloat16*)fcB_p, out,
            DIM, FCK, 0, 0, 0);
    }
}